// round 10
// baseline (speedup 1.0000x reference)
#include <cuda_runtime.h>
#include <cuda_bf16.h>
#include <cstdint>

// out[r][c] = in[2r+1][2c+1], in: 8192x8192 fp32, out: 4096x4096 fp32.
// R2 memory pattern (best: 31.2us steady state = mixed-stream DRAM ceiling),
// reshaped to TPB=512 / UNROLL=2: same byte-identical access pattern,
// half the index arithmetic, larger per-SM front-batched load cohort.
//   reads:  8 front-batched __ldcs LDG.128 per thread (evict-first stream)
//   writes: 4 contiguous STG.128 per thread (default write-back)

#define N_IN   8192
#define N_OUT  4096
#define F4_ROW (N_OUT / 4)   // 1024 output float4s per row
#define TPB    512
#define UNROLL 2             // F4_ROW / TPB

__global__ __launch_bounds__(TPB) void decimate2_kernel(
    const float4* __restrict__ in, float4* __restrict__ out)
{
    const int orow = blockIdx.x;
    const int tid  = threadIdx.x;

    const float4* in_row  = in  + (size_t)(2 * orow + 1) * (N_IN / 4);
    float4*       out_row = out + (size_t)orow * F4_ROW;

    float4 a[UNROLL], b[UNROLL];

    // Front-batched loads: 4 independent LDG.128 in flight per thread
    // (x512 threads/CTA -> same cohort depth per SM as R2).
#pragma unroll
    for (int k = 0; k < UNROLL; k++) {
        const int oc4 = tid + k * TPB;
        a[k] = __ldcs(&in_row[2 * oc4]);
        b[k] = __ldcs(&in_row[2 * oc4 + 1]);
    }

#pragma unroll
    for (int k = 0; k < UNROLL; k++) {
        const int oc4 = tid + k * TPB;
        float4 r;
        r.x = a[k].y;   // odd col 8*oc4+1
        r.y = a[k].w;   // odd col 8*oc4+3
        r.z = b[k].y;   // odd col 8*oc4+5
        r.w = b[k].w;   // odd col 8*oc4+7
        out_row[oc4] = r;
    }
}

extern "C" void kernel_launch(void* const* d_in, const int* in_sizes, int n_in,
                              void* d_out, int out_size)
{
    const float4* in  = (const float4*)d_in[0];
    float4*       out = (float4*)d_out;

    decimate2_kernel<<<N_OUT, TPB>>>(in, out);
}